// round 5
// baseline (speedup 1.0000x reference)
#include <cuda_runtime.h>
#include <math.h>

#define NP 10000
#define NG 1000
#define NC 80

// ---- persistent device scratch (module-static, no runtime alloc) ----
__device__ float    g_cost[(size_t)NG * NP];   // column-major: g_cost[j*NP + i]
__device__ float    g_cls [(size_t)NC * NP];   // transposed cls cost table [c][i]
__device__ int      g_valid[NP];
__device__ unsigned g_mbits[NP * 32];          // match matrix bitset, row-major
__device__ int      g_rowcnt[NP];
__device__ int      g_colcnt[NG];
__device__ int      g_addcnt[NP];              // # of +100000 additions applied to row
__device__ int      g_prior[NP];

__device__ __forceinline__ float cls_cost_f(float x) {
    float p   = (x >= 0.f) ? (1.f / (1.f + expf(-x))) : (expf(x) / (1.f + expf(x)));
    float omp = 1.f - p;
    float pos = -logf(p + 1e-12f) * 0.25f * (omp * omp);
    float neg = -log1pf(-(p - 1e-12f)) * 0.75f * (p * p);
    return (pos - neg) * 2.0f;
}

__device__ __forceinline__ bool cost_less(float av, int ai, float bv, int bi) {
    return (av < bv) || (av == bv && ai < bi);
}

// exact replication of jax's sequential float32 accumulation of +100000
__device__ __forceinline__ float addK(float v, int k) {
    #pragma unroll 1
    for (int t = 0; t < k; t++) v += 100000.0f;
    return v;
}

__global__ void init_kernel() {
    int t = blockIdx.x * blockDim.x + threadIdx.x;
    if (t < NP * 32) g_mbits[t] = 0u;
    if (t < NP) { g_rowcnt[t] = 0; g_addcnt[t] = 0; g_prior[t] = 0; }
    if (t < NG) g_colcnt[t] = 0;
}

__global__ void cls_kernel(const float* __restrict__ logits) {
    int i = blockIdx.x * blockDim.x + threadIdx.x;
    if (i >= NP) return;
    const float4* row = reinterpret_cast<const float4*>(logits + (size_t)i * NC);
    #pragma unroll
    for (int q = 0; q < NC / 4; q++) {
        float4 v = row[q];
        g_cls[(q * 4 + 0) * NP + i] = cls_cost_f(v.x);
        g_cls[(q * 4 + 1) * NP + i] = cls_cost_f(v.y);
        g_cls[(q * 4 + 2) * NP + i] = cls_cost_f(v.z);
        g_cls[(q * 4 + 3) * NP + i] = cls_cost_f(v.w);
    }
}

__global__ void valid_kernel(const float* __restrict__ pb, const float* __restrict__ gb) {
    __shared__ float4 sg[NG];
    for (int j = threadIdx.x; j < NG; j += blockDim.x)
        sg[j] = reinterpret_cast<const float4*>(gb)[j];
    __syncthreads();
    int i = blockIdx.x * blockDim.x + threadIdx.x;
    if (i >= NP) return;
    float4 p = reinterpret_cast<const float4*>(pb)[i];
    float pcx = (p.x + p.z) * 0.5f, pcy = (p.y + p.w) * 0.5f;
    int v = 0;
    for (int j = 0; j < NG; j++) {
        float4 g = sg[j];
        bool ib = (pcx > g.x) && (pcx < g.z) && (pcy > g.y) && (pcy < g.w);
        float gcx = (g.x + g.z) * 0.5f, gcy = (g.y + g.w) * 0.5f;
        float gw = g.z - g.x, gh = g.w - g.y;
        bool ic = (pcx > gcx - 2.5f * gw) && (pcx < gcx + 2.5f * gw) &&
                  (pcy > gcy - 2.5f * gh) && (pcy < gcy + 2.5f * gh);
        if (ib || ic) { v = 1; break; }
    }
    g_valid[i] = v;
}

__device__ __forceinline__ void merge_lists(float* aio, float* acv, int* aci,
                                            const float* bio, const float* bcv, const int* bci) {
    float rio[5];
    { int ia = 0, ib = 0;
      #pragma unroll
      for (int q = 0; q < 5; q++) rio[q] = (aio[ia] >= bio[ib]) ? aio[ia++] : bio[ib++];
    }
    float rcv[5]; int rci[5];
    { int ia = 0, ib = 0;
      #pragma unroll
      for (int q = 0; q < 5; q++) {
          if (cost_less(acv[ia], aci[ia], bcv[ib], bci[ib])) { rcv[q] = acv[ia]; rci[q] = aci[ia]; ia++; }
          else                                               { rcv[q] = bcv[ib]; rci[q] = bci[ib]; ib++; }
      }
    }
    #pragma unroll
    for (int q = 0; q < 5; q++) { aio[q] = rio[q]; acv[q] = rcv[q]; aci[q] = rci[q]; }
}

// One block per gt. Computes cost column, top-5 ious (-> dynamic_k),
// top-5 lowest costs (-> initial assignments).
__global__ void pair_kernel(const float* __restrict__ pb, const float* __restrict__ gb,
                            const int* __restrict__ labels,
                            const int* __restrict__ p_h, const int* __restrict__ p_w) {
    int j = blockIdx.x;
    __shared__ float s_io[256 * 5];
    __shared__ float s_cv[256 * 5];
    __shared__ int   s_ci[256 * 5];

    float fw = (float)(*p_w);
    float fh = (float)(*p_h);
    float4 g = reinterpret_cast<const float4*>(gb)[j];
    int lab = labels[j];
    float gx1 = g.x, gy1 = g.y, gx2 = g.z, gy2 = g.w;
    float ag  = (gx2 - gx1) * (gy2 - gy1);
    float gcx = (gx1 + gx2) * 0.5f, gcy = (gy1 + gy2) * 0.5f;
    float gw  = gx2 - gx1, gh = gy2 - gy1;
    float n0 = gx1 / fw, n1 = gy1 / fh, n2 = gx2 / fw, n3 = gy2 / fh;
    const float* __restrict__ clsCol  = g_cls + (size_t)lab * NP;
    float*       __restrict__ costCol = g_cost + (size_t)j * NP;

    float tio[5], tcv[5]; int tci[5];
    #pragma unroll
    for (int q = 0; q < 5; q++) { tio[q] = -3.4e38f; tcv[q] = 3.4e38f; tci[q] = 0x7fffffff; }

    for (int i = threadIdx.x; i < NP; i += 256) {
        float4 p = reinterpret_cast<const float4*>(pb)[i];
        float ap  = (p.z - p.x) * (p.w - p.y);
        float ltx = fmaxf(p.x, gx1), lty = fmaxf(p.y, gy1);
        float rbx = fminf(p.z, gx2), rby = fminf(p.w, gy2);
        float iw = fmaxf(rbx - ltx, 0.f), ih = fmaxf(rby - lty, 0.f);
        float inter = iw * ih;
        float uni = ap + ag - inter;
        float iou = inter / fmaxf(uni, 1e-12f);
        float ex = fmaxf(fmaxf(p.z, gx2) - fminf(p.x, gx1), 0.f);
        float ey = fmaxf(fmaxf(p.w, gy2) - fminf(p.y, gy1), 0.f);
        float enc = ex * ey;
        float giou = iou - (enc - uni) / fmaxf(enc, 1e-12f);
        float l1 = fabsf(p.x / fw - n0) + fabsf(p.y / fh - n1) +
                   fabsf(p.z / fw - n2) + fabsf(p.w / fh - n3);
        float cost = clsCol[i] + l1 * 5.0f + (-giou * 2.0f);
        float pcx = (p.x + p.z) * 0.5f, pcy = (p.y + p.w) * 0.5f;
        bool ib = (pcx > gx1) && (pcx < gx2) && (pcy > gy1) && (pcy < gy2);
        bool ic = (pcx > gcx - 2.5f * gw) && (pcx < gcx + 2.5f * gw) &&
                  (pcy > gcy - 2.5f * gh) && (pcy < gcy + 2.5f * gh);
        cost = cost + ((ib && ic) ? 0.0f : 100.0f);
        cost = cost + (g_valid[i] ? 0.0f : 10000.0f);
        costCol[i] = cost;

        if (iou > tio[4]) {
            tio[4] = iou;
            for (int t = 4; t > 0 && tio[t] > tio[t - 1]; t--) {
                float tmp = tio[t]; tio[t] = tio[t - 1]; tio[t - 1] = tmp;
            }
        }
        if (cost_less(cost, i, tcv[4], tci[4])) {
            tcv[4] = cost; tci[4] = i;
            for (int t = 4; t > 0 && cost_less(tcv[t], tci[t], tcv[t - 1], tci[t - 1]); t--) {
                float tv = tcv[t]; tcv[t] = tcv[t - 1]; tcv[t - 1] = tv;
                int   ti = tci[t]; tci[t] = tci[t - 1]; tci[t - 1] = ti;
            }
        }
    }

    int t = threadIdx.x;
    #pragma unroll
    for (int q = 0; q < 5; q++) { s_io[t * 5 + q] = tio[q]; s_cv[t * 5 + q] = tcv[q]; s_ci[t * 5 + q] = tci[q]; }
    __syncthreads();
    for (int stride = 128; stride > 0; stride >>= 1) {
        if (t < stride)
            merge_lists(&s_io[t * 5], &s_cv[t * 5], &s_ci[t * 5],
                        &s_io[(t + stride) * 5], &s_cv[(t + stride) * 5], &s_ci[(t + stride) * 5]);
        __syncthreads();
    }
    if (t == 0) {
        float s = 0.f;                       // descending-order sequential sum (matches jnp)
        for (int q = 0; q < 5; q++) s += s_io[q];
        int dk = (int)s;                     // truncation toward zero, like astype(int32)
        if (dk < 1) dk = 1;
        if (dk > 5) dk = 5;
        for (int q = 0; q < dk; q++) {
            int p = s_ci[q];
            atomicOr(&g_mbits[p * 32 + (j >> 5)], 1u << (j & 31));
            atomicAdd(&g_rowcnt[p], 1);
        }
        g_colcnt[j] = dk;
    }
}

// Pre-loop: rows matched to >1 gt collapse to one_hot(cmin) and are marked prior.
__global__ void fix_kernel() {
    int i = blockIdx.x * blockDim.x + threadIdx.x;
    if (i >= NP) return;
    if (g_rowcnt[i] > 1) {
        float bv = 3.4e38f; int bj = 0;
        for (int j = 0; j < NG; j++) {
            float v = g_cost[(size_t)j * NP + i];
            if (v < bv) { bv = v; bj = j; }
        }
        g_prior[i] = 1;
        for (int w = 0; w < 32; w++) {
            unsigned m = g_mbits[i * 32 + w];
            while (m) { int b = __ffs(m) - 1; m &= m - 1; atomicSub(&g_colcnt[w * 32 + b], 1); }
            g_mbits[i * 32 + w] = 0u;
        }
        g_mbits[i * 32 + (bj >> 5)] = 1u << (bj & 31);
        atomicAdd(&g_colcnt[bj], 1);
        g_rowcnt[i] = 1;
    }
}

// Device-side while-loop (single persistent block, 1024 threads).
__global__ void loop_kernel() {
    __shared__ int s_flagUn, s_numU, s_flagRow2;
    __shared__ short s_list[NG];
    __shared__ int   s_pos[NG];
    __shared__ unsigned char s_add[NP];
    int tid = threadIdx.x;
    int wid = tid >> 5, lane = tid & 31;

    for (int iter = 0; iter < 4096; iter++) {
        if (tid == 0) { s_flagUn = 0; s_numU = 0; s_flagRow2 = 0; }
        __syncthreads();
        for (int gg = tid; gg < NG; gg += 1024) if (g_colcnt[gg] == 0) s_flagUn = 1;
        __syncthreads();
        if (!s_flagUn) break;

        // c += 100000 * matched_q  (row-constant, tracked as a count)
        for (int i = tid; i < NP; i += 1024) {
            int a = g_addcnt[i];
            if (g_rowcnt[i] > 0) { a += 1; g_addcnt[i] = a; }
            s_add[i] = (unsigned char)(a > 255 ? 255 : a);
        }
        for (int gg = tid; gg < NG; gg += 1024)
            if (g_colcnt[gg] == 0) { int u = atomicAdd(&s_numU, 1); s_list[u] = (short)gg; }
        __syncthreads();
        int nU = s_numU;

        // warp-per-unmatched-gt column argmin (lowest index on ties, like jnp.argmin)
        for (int u = wid; u < nU; u += 32) {
            int gg = s_list[u];
            const float* col = g_cost + (size_t)gg * NP;
            float bv = 3.4e38f; int bi = 0x7fffffff;
            for (int i = lane; i < NP; i += 32) {
                float v = addK(col[i], (int)s_add[i]);
                if (v < bv || (v == bv && i < bi)) { bv = v; bi = i; }
            }
            #pragma unroll
            for (int off = 16; off; off >>= 1) {
                float ov = __shfl_down_sync(0xffffffffu, bv, off);
                int   oi = __shfl_down_sync(0xffffffffu, bi, off);
                if (ov < bv || (ov == bv && oi < bi)) { bv = ov; bi = oi; }
            }
            if (lane == 0) s_pos[u] = bi;
        }
        __syncthreads();
        for (int u = tid; u < nU; u += 1024) {
            int gg = s_list[u]; int p = s_pos[u];
            atomicOr(&g_mbits[p * 32 + (gg >> 5)], 1u << (gg & 31));
            atomicAdd(&g_rowcnt[p], 1);
            g_colcnt[gg] = 1;
        }
        __syncthreads();
        for (int i = tid; i < NP; i += 1024) if (g_rowcnt[i] > 1) s_flagRow2 = 1;
        __syncthreads();
        if (s_flagRow2) {
            // m_fix: every prior row -> full one_hot(argmin_j (cost + pen)), exact semantics:
            // clear ALL other bits in the row (incl. any just-assigned one), fix colcnt.
            for (int i = tid; i < NP; i += 1024) {
                if (g_prior[i]) {
                    int k = (int)s_add[i];
                    float bv = 3.4e38f; int bj = 0;
                    for (int j = 0; j < NG; j++) {
                        float v = addK(g_cost[(size_t)j * NP + i], k);
                        if (v < bv) { bv = v; bj = j; }
                    }
                    int bjw = bj >> 5;
                    unsigned bjb = 1u << (bj & 31);
                    bool hadbj = false;
                    for (int w = 0; w < 32; w++) {
                        unsigned m = g_mbits[i * 32 + w];
                        if (!m) continue;
                        unsigned keep = (w == bjw) ? bjb : 0u;
                        if (m & keep) hadbj = true;
                        unsigned clr = m & ~keep;
                        while (clr) {
                            int b = __ffs(clr) - 1; clr &= clr - 1;
                            atomicSub(&g_colcnt[w * 32 + b], 1);
                        }
                        g_mbits[i * 32 + w] = m & keep;
                    }
                    if (!hadbj) {
                        g_mbits[i * 32 + bjw] |= bjb;
                        atomicAdd(&g_colcnt[bj], 1);
                    }
                    g_rowcnt[i] = 1;
                }
            }
            __syncthreads();
        }
    }
}

__global__ void out_kernel(float* __restrict__ out) {
    int i = blockIdx.x * blockDim.x + threadIdx.x;
    if (i >= NP) return;
    int fg = g_rowcnt[i] > 0;
    out[i] = fg ? 1.0f : 0.0f;
    int mg = 0;
    if (fg) {
        for (int w = 0; w < 32; w++) {
            unsigned m = g_mbits[i * 32 + w];
            if (m) { mg = w * 32 + (__ffs(m) - 1); break; }
        }
    }
    out[NP + i] = (float)mg;
}

extern "C" void kernel_launch(void* const* d_in, const int* in_sizes, int n_in,
                              void* d_out, int out_size) {
    const float* logits = (const float*)d_in[0];
    const float* pb     = (const float*)d_in[1];
    const float* gb     = (const float*)d_in[2];
    const int*   labels = (const int*)  d_in[3];
    const int*   p_h    = (const int*)  d_in[4];
    const int*   p_w    = (const int*)  d_in[5];

    init_kernel<<<(NP * 32 + 255) / 256, 256>>>();
    cls_kernel<<<(NP + 255) / 256, 256>>>(logits);
    valid_kernel<<<(NP + 255) / 256, 256>>>(pb, gb);
    pair_kernel<<<NG, 256>>>(pb, gb, labels, p_h, p_w);
    fix_kernel<<<(NP + 255) / 256, 256>>>();
    loop_kernel<<<1, 1024>>>();
    out_kernel<<<(NP + 255) / 256, 256>>>((float*)d_out);
}

// round 6
// speedup vs baseline: 1.4259x; 1.4259x over previous
#include <cuda_runtime.h>
#include <math.h>

#define NP 10000
#define NG 1000
#define NC 80
#define PMAX 2500   // max rows with >=2 initial assignments (sum dk <= 5000)

// ---- persistent device scratch ----
__device__ float    g_cost[(size_t)NG * NP];     // column-major: g_cost[j*NP + i]
__device__ float    g_cls [(size_t)NC * NP];     // transposed cls cost table
__device__ float4   g_pn  [NP];                  // pred boxes / factor (normalized)
__device__ float    g_vadd[NP];                  // valid ? 0 : 10000
__device__ unsigned g_mbits[NP * 32];            // match bitset, row-major
__device__ int      g_rowcnt[NP];
__device__ int      g_colcnt[NG];
__device__ int      g_cand[NG * 5];              // per-column top-5 lowest-cost pred idx (sorted)
__device__ int      g_priorCount;
__device__ int      g_priorList[PMAX];
__device__ int      g_priorCur [PMAX];
__device__ float    g_priorCost[(size_t)PMAX * NG];  // row-major gathered prior rows

__device__ __forceinline__ float cls_cost_f(float x) {
    float p   = (x >= 0.f) ? (1.f / (1.f + expf(-x))) : (expf(x) / (1.f + expf(x)));
    float omp = 1.f - p;
    float pos = -logf(p + 1e-12f) * 0.25f * (omp * omp);
    float neg = -log1pf(-(p - 1e-12f)) * 0.75f * (p * p);
    return (pos - neg) * 2.0f;
}

__device__ __forceinline__ bool cost_less(float av, int ai, float bv, int bi) {
    return (av < bv) || (av == bv && ai < bi);
}

__global__ void init_kernel() {
    int t = blockIdx.x * blockDim.x + threadIdx.x;
    if (t < NP * 32) g_mbits[t] = 0u;
    if (t < NP) g_rowcnt[t] = 0;
    if (t < NG) g_colcnt[t] = 0;
    if (t == 0) g_priorCount = 0;
}

__global__ void cls_kernel(const float* __restrict__ logits) {
    int i = blockIdx.x * blockDim.x + threadIdx.x;
    if (i >= NP) return;
    const float4* row = reinterpret_cast<const float4*>(logits + (size_t)i * NC);
    #pragma unroll
    for (int q = 0; q < NC / 4; q++) {
        float4 v = row[q];
        g_cls[(q * 4 + 0) * NP + i] = cls_cost_f(v.x);
        g_cls[(q * 4 + 1) * NP + i] = cls_cost_f(v.y);
        g_cls[(q * 4 + 2) * NP + i] = cls_cost_f(v.z);
        g_cls[(q * 4 + 3) * NP + i] = cls_cost_f(v.w);
    }
}

// Per-pred precompute: normalized box (exact p/factor), validity flag as float.
__global__ void prep_kernel(const float* __restrict__ pb, const float* __restrict__ gb,
                            const int* __restrict__ p_h, const int* __restrict__ p_w) {
    __shared__ float4 sg[NG];
    for (int j = threadIdx.x; j < NG; j += blockDim.x)
        sg[j] = reinterpret_cast<const float4*>(gb)[j];
    __syncthreads();
    int i = blockIdx.x * blockDim.x + threadIdx.x;
    if (i >= NP) return;
    float fw = (float)(*p_w), fh = (float)(*p_h);
    float4 p = reinterpret_cast<const float4*>(pb)[i];
    float4 pn;
    pn.x = p.x / fw; pn.y = p.y / fh; pn.z = p.z / fw; pn.w = p.w / fh;
    g_pn[i] = pn;
    float pcx = (p.x + p.z) * 0.5f, pcy = (p.y + p.w) * 0.5f;
    int v = 0;
    for (int j = 0; j < NG; j++) {
        float4 g = sg[j];
        bool ib = (pcx > g.x) && (pcx < g.z) && (pcy > g.y) && (pcy < g.w);
        float gcx = (g.x + g.z) * 0.5f, gcy = (g.y + g.w) * 0.5f;
        float gw = g.z - g.x, gh = g.w - g.y;
        bool ic = (pcx > gcx - 2.5f * gw) && (pcx < gcx + 2.5f * gw) &&
                  (pcy > gcy - 2.5f * gh) && (pcy < gcy + 2.5f * gh);
        if (ib || ic) { v = 1; break; }
    }
    g_vadd[i] = v ? 0.0f : 10000.0f;
}

__device__ __forceinline__ void merge_lists(float* aio, float* acv, int* aci,
                                            const float* bio, const float* bcv, const int* bci) {
    float rio[5];
    { int ia = 0, ib = 0;
      #pragma unroll
      for (int q = 0; q < 5; q++) rio[q] = (aio[ia] >= bio[ib]) ? aio[ia++] : bio[ib++];
    }
    float rcv[5]; int rci[5];
    { int ia = 0, ib = 0;
      #pragma unroll
      for (int q = 0; q < 5; q++) {
          if (cost_less(acv[ia], aci[ia], bcv[ib], bci[ib])) { rcv[q] = acv[ia]; rci[q] = aci[ia]; ia++; }
          else                                               { rcv[q] = bcv[ib]; rci[q] = bci[ib]; ib++; }
      }
    }
    #pragma unroll
    for (int q = 0; q < 5; q++) { aio[q] = rio[q]; acv[q] = rcv[q]; aci[q] = rci[q]; }
}

// One block per gt. Cost column + top-5 ious (dynamic_k) + top-5 lowest costs.
__global__ void pair_kernel(const float* __restrict__ pb, const float* __restrict__ gb,
                            const int* __restrict__ labels,
                            const int* __restrict__ p_h, const int* __restrict__ p_w) {
    int j = blockIdx.x;
    __shared__ float s_io[256 * 5];
    __shared__ float s_cv[256 * 5];
    __shared__ int   s_ci[256 * 5];

    float fw = (float)(*p_w), fh = (float)(*p_h);
    float4 g = reinterpret_cast<const float4*>(gb)[j];
    int lab = labels[j];
    float gx1 = g.x, gy1 = g.y, gx2 = g.z, gy2 = g.w;
    float ag  = (gx2 - gx1) * (gy2 - gy1);
    float gcx = (gx1 + gx2) * 0.5f, gcy = (gy1 + gy2) * 0.5f;
    float gw  = gx2 - gx1, gh = gy2 - gy1;
    float n0 = gx1 / fw, n1 = gy1 / fh, n2 = gx2 / fw, n3 = gy2 / fh;
    float lo_x = gcx - 2.5f * gw, hi_x = gcx + 2.5f * gw;
    float lo_y = gcy - 2.5f * gh, hi_y = gcy + 2.5f * gh;
    const float* __restrict__ clsCol  = g_cls + (size_t)lab * NP;
    float*       __restrict__ costCol = g_cost + (size_t)j * NP;

    float tio[5], tcv[5]; int tci[5];
    #pragma unroll
    for (int q = 0; q < 5; q++) { tio[q] = -3.4e38f; tcv[q] = 3.4e38f; tci[q] = 0x7fffffff; }

    for (int i = threadIdx.x; i < NP; i += 256) {
        float4 p  = reinterpret_cast<const float4*>(pb)[i];
        float4 pn = g_pn[i];
        float ap  = (p.z - p.x) * (p.w - p.y);
        float ltx = fmaxf(p.x, gx1), lty = fmaxf(p.y, gy1);
        float rbx = fminf(p.z, gx2), rby = fminf(p.w, gy2);
        float iw = fmaxf(rbx - ltx, 0.f), ih = fmaxf(rby - lty, 0.f);
        float inter = iw * ih;
        float uni = ap + ag - inter;
        float iou = inter / fmaxf(uni, 1e-12f);
        float ex = fmaxf(fmaxf(p.z, gx2) - fminf(p.x, gx1), 0.f);
        float ey = fmaxf(fmaxf(p.w, gy2) - fminf(p.y, gy1), 0.f);
        float enc = ex * ey;
        float giou = iou - (enc - uni) / fmaxf(enc, 1e-12f);
        float l1 = fabsf(pn.x - n0) + fabsf(pn.y - n1) +
                   fabsf(pn.z - n2) + fabsf(pn.w - n3);
        float cost = clsCol[i] + l1 * 5.0f + (-giou * 2.0f);
        float pcx = (p.x + p.z) * 0.5f, pcy = (p.y + p.w) * 0.5f;
        bool ib = (pcx > gx1) && (pcx < gx2) && (pcy > gy1) && (pcy < gy2);
        bool ic = (pcx > lo_x) && (pcx < hi_x) && (pcy > lo_y) && (pcy < hi_y);
        cost = cost + ((ib && ic) ? 0.0f : 100.0f);
        cost = cost + g_vadd[i];
        costCol[i] = cost;

        if (iou > tio[4]) {
            tio[4] = iou;
            for (int t = 4; t > 0 && tio[t] > tio[t - 1]; t--) {
                float tmp = tio[t]; tio[t] = tio[t - 1]; tio[t - 1] = tmp;
            }
        }
        if (cost_less(cost, i, tcv[4], tci[4])) {
            tcv[4] = cost; tci[4] = i;
            for (int t = 4; t > 0 && cost_less(tcv[t], tci[t], tcv[t - 1], tci[t - 1]); t--) {
                float tv = tcv[t]; tcv[t] = tcv[t - 1]; tcv[t - 1] = tv;
                int   ti = tci[t]; tci[t] = tci[t - 1]; tci[t - 1] = ti;
            }
        }
    }

    int t = threadIdx.x;
    #pragma unroll
    for (int q = 0; q < 5; q++) { s_io[t * 5 + q] = tio[q]; s_cv[t * 5 + q] = tcv[q]; s_ci[t * 5 + q] = tci[q]; }
    __syncthreads();
    for (int stride = 128; stride > 0; stride >>= 1) {
        if (t < stride)
            merge_lists(&s_io[t * 5], &s_cv[t * 5], &s_ci[t * 5],
                        &s_io[(t + stride) * 5], &s_cv[(t + stride) * 5], &s_ci[(t + stride) * 5]);
        __syncthreads();
    }
    if (t == 0) {
        float s = 0.f;
        for (int q = 0; q < 5; q++) s += s_io[q];
        int dk = (int)s;
        if (dk < 1) dk = 1;
        if (dk > 5) dk = 5;
        for (int q = 0; q < 5; q++) g_cand[j * 5 + q] = s_ci[q];
        for (int q = 0; q < dk; q++) {
            int p = s_ci[q];
            atomicOr(&g_mbits[p * 32 + (j >> 5)], 1u << (j & 31));
            atomicAdd(&g_rowcnt[p], 1);
        }
        g_colcnt[j] = dk;
    }
}

// Pre-loop: over-assigned rows collapse to one_hot(cmin), recorded as prior rows.
__global__ void fix_kernel() {
    int i = blockIdx.x * blockDim.x + threadIdx.x;
    if (i >= NP) return;
    if (g_rowcnt[i] > 1) {
        float bv = 3.4e38f; int bj = 0;
        for (int j = 0; j < NG; j++) {
            float v = g_cost[(size_t)j * NP + i];
            if (v < bv) { bv = v; bj = j; }
        }
        for (int w = 0; w < 32; w++) {
            unsigned m = g_mbits[i * 32 + w];
            while (m) { int b = __ffs(m) - 1; m &= m - 1; atomicSub(&g_colcnt[w * 32 + b], 1); }
            g_mbits[i * 32 + w] = 0u;
        }
        g_mbits[i * 32 + (bj >> 5)] = 1u << (bj & 31);
        atomicAdd(&g_colcnt[bj], 1);
        g_rowcnt[i] = 1;
        int p = atomicAdd(&g_priorCount, 1);
        g_priorList[p] = i;
        g_priorCur[p]  = bj;
    }
}

// Gather prior rows into compact row-major scratch (coalesced writes).
__global__ void gather_kernel() {
    int p = blockIdx.x;
    if (p >= g_priorCount) return;
    int i = g_priorList[p];
    for (int j = threadIdx.x; j < NG; j += blockDim.x)
        g_priorCost[(size_t)p * NG + j] = g_cost[(size_t)j * NP + i];
}

// Device-side while-loop (single block, 1024 threads).
// Key facts (proved exact): matched-row penalized values (>= ~99950) can never
// win a column argmin against unmatched raw costs (<= ~10130), and addK(v,0)=v,
// so column argmins = argmin of RAW cost over snapshot-unmatched rows.
// Prior rows all share penalty count k=iter+1; +100000.0f accumulated in place
// per iteration replicates jax's sequential float accumulation bit-exactly.
__global__ void loop_kernel() {
    __shared__ unsigned s_mb[(NP + 31) / 32];
    __shared__ short s_list[NG], s_sel[NG], s_fb[NG];
    __shared__ short s_pbj[PMAX];
    __shared__ int s_nA, s_nFb, s_conflict;
    int tid = threadIdx.x, wid = tid >> 5, lane = tid & 31;
    int P = g_priorCount;

    if (tid == 0) s_conflict = 0;
    for (int w = tid; w < (NP + 31) / 32; w += 1024) s_mb[w] = 0u;
    __syncthreads();
    for (int i = tid; i < NP; i += 1024)
        if (g_rowcnt[i] > 0) atomicOr(&s_mb[i >> 5], 1u << (i & 31));
    __syncthreads();

    for (int iter = 0; iter < 4096; iter++) {
        if (tid == 0) { s_nA = 0; s_nFb = 0; }
        __syncthreads();
        // build unmatched-column list
        for (int gg = tid; gg < NG; gg += 1024)
            if (g_colcnt[gg] == 0) { int u = atomicAdd(&s_nA, 1); s_list[u] = (short)gg; }
        __syncthreads();
        int nA = s_nA;
        if (nA == 0) break;

        // 1. prior rows: accumulate +100000 in place AND row argmin (warp per row)
        for (int p = wid; p < P; p += 32) {
            float* row = g_priorCost + (size_t)p * NG;
            float bv = 3.4e38f; int bj = 0x7fffffff;
            for (int jj = lane; jj < NG; jj += 32) {
                float v = row[jj] + 100000.0f;
                row[jj] = v;
                if (v < bv || (v == bv && jj < bj)) { bv = v; bj = jj; }
            }
            #pragma unroll
            for (int off = 16; off; off >>= 1) {
                float ov = __shfl_down_sync(0xffffffffu, bv, off);
                int   oj = __shfl_down_sync(0xffffffffu, bj, off);
                if (ov < bv || (ov == bv && oj < bj)) { bv = ov; bj = oj; }
            }
            if (lane == 0) s_pbj[p] = (short)bj;
        }

        // 2. candidate walk (thread per unmatched column)
        for (int u = tid; u < nA; u += 1024) {
            int gg = s_list[u];
            int chosen = -1;
            #pragma unroll
            for (int q = 0; q < 5; q++) {
                int r = g_cand[gg * 5 + q];
                if (chosen < 0 && !((s_mb[r >> 5] >> (r & 31)) & 1u)) chosen = r;
            }
            if (chosen < 0) { int f = atomicAdd(&s_nFb, 1); s_fb[f] = (short)u; }
            s_sel[u] = (short)chosen;
        }
        __syncthreads();

        // 3. fallback full column scans (warp per column), skipping matched rows
        int nFb = s_nFb;
        for (int f = wid; f < nFb; f += 32) {
            int u = s_fb[f]; int gg = s_list[u];
            const float* col = g_cost + (size_t)gg * NP;
            float bv = 3.4e38f; int bi = 0x7fffffff;
            for (int i = lane; i < NP; i += 32) {
                if (!((s_mb[i >> 5] >> (i & 31)) & 1u)) {
                    float v = col[i];
                    if (v < bv || (v == bv && i < bi)) { bv = v; bi = i; }
                }
            }
            #pragma unroll
            for (int off = 16; off; off >>= 1) {
                float ov = __shfl_down_sync(0xffffffffu, bv, off);
                int   oi = __shfl_down_sync(0xffffffffu, bi, off);
                if (ov < bv || (ov == bv && oi < bi)) { bv = ov; bi = oi; }
            }
            if (lane == 0) s_sel[u] = (short)bi;
        }
        __syncthreads();

        // 4. apply assignments
        for (int u = tid; u < nA; u += 1024) {
            int r = (int)s_sel[u];
            if (r < 0) continue;
            int gg = s_list[u];
            atomicOr(&g_mbits[r * 32 + (gg >> 5)], 1u << (gg & 31));
            int old = atomicAdd(&g_rowcnt[r], 1);
            if (old >= 1) atomicAdd(&s_conflict, 1);
            g_colcnt[gg] = 1;
        }
        __syncthreads();
        for (int u = tid; u < nA; u += 1024) {
            int r = (int)s_sel[u];
            if (r >= 0) atomicOr(&s_mb[r >> 5], 1u << (r & 31));
        }
        __syncthreads();

        // 5. m_fix: all prior rows -> one_hot(cmin2) when any row conflicted
        if (s_conflict > 0) {
            for (int p = tid; p < P; p += 1024) {
                int bj = (int)s_pbj[p];
                int cur = g_priorCur[p];
                if (bj != cur) {
                    int i = g_priorList[p];
                    g_mbits[i * 32 + (cur >> 5)] &= ~(1u << (cur & 31));
                    g_mbits[i * 32 + (bj >> 5)]  |=  (1u << (bj & 31));
                    atomicSub(&g_colcnt[cur], 1);
                    atomicAdd(&g_colcnt[bj], 1);
                    g_priorCur[p] = bj;
                }
            }
        }
        __syncthreads();
    }
}

__global__ void out_kernel(float* __restrict__ out) {
    int i = blockIdx.x * blockDim.x + threadIdx.x;
    if (i >= NP) return;
    int fg = g_rowcnt[i] > 0;
    out[i] = fg ? 1.0f : 0.0f;
    int mg = 0;
    if (fg) {
        for (int w = 0; w < 32; w++) {
            unsigned m = g_mbits[i * 32 + w];
            if (m) { mg = w * 32 + (__ffs(m) - 1); break; }
        }
    }
    out[NP + i] = (float)mg;
}

extern "C" void kernel_launch(void* const* d_in, const int* in_sizes, int n_in,
                              void* d_out, int out_size) {
    const float* logits = (const float*)d_in[0];
    const float* pb     = (const float*)d_in[1];
    const float* gb     = (const float*)d_in[2];
    const int*   labels = (const int*)  d_in[3];
    const int*   p_h    = (const int*)  d_in[4];
    const int*   p_w    = (const int*)  d_in[5];

    init_kernel<<<(NP * 32 + 255) / 256, 256>>>();
    cls_kernel<<<(NP + 255) / 256, 256>>>(logits);
    prep_kernel<<<(NP + 255) / 256, 256>>>(pb, gb, p_h, p_w);
    pair_kernel<<<NG, 256>>>(pb, gb, labels, p_h, p_w);
    fix_kernel<<<(NP + 255) / 256, 256>>>();
    gather_kernel<<<PMAX, 128>>>();
    loop_kernel<<<1, 1024>>>();
    out_kernel<<<(NP + 255) / 256, 256>>>((float*)d_out);
}